// round 2
// baseline (speedup 1.0000x reference)
#include <cuda_runtime.h>
#include <cstddef>

#define NQ    40000
#define D     256
#define BEVH  200
#define BEVW  200
#define NH    8
#define NP    8
#define HD    32
#define DFF   1024

typedef unsigned long long u64;

// ---------------- scratch (static device globals; no allocation) ------------
__device__ float g_off [ (size_t)NQ * (NH*NP*2) ];   // 40000 x 128
__device__ float g_attn[ (size_t)NQ * (NH*NP)   ];   // 40000 x 64
__device__ float g_ref [ (size_t)NQ * 2         ];   // 40000 x 2
__device__ float g_vsum[ (size_t)NQ * D         ];   // 40000 x 256 (val0+val1)
__device__ float g_att [ (size_t)NQ * D         ];   // 40000 x 256 (attended sum)
__device__ float g_ffh [ (size_t)NQ * DFF       ];   // 40000 x 1024

// ---------------- f32x2 packed-FMA helpers (sm_103a FFMA2) ------------------
__device__ __forceinline__ u64 pack2(float lo, float hi) {
    u64 r;
    asm("mov.b64 %0, {%1, %2};" : "=l"(r) : "f"(lo), "f"(hi));
    return r;
}
__device__ __forceinline__ void unpack2(u64 v, float& lo, float& hi) {
    asm("mov.b64 {%0, %1}, %2;" : "=f"(lo), "=f"(hi) : "l"(v));
}
__device__ __forceinline__ void fma2(u64& d, u64 a, u64 b) {
    asm("fma.rn.f32x2 %0, %1, %2, %0;" : "+l"(d) : "l"(a), "l"(b));
}

// ---------------- generic tiled fp32 GEMM + fused epilogue ------------------
// C[M,N] = (A (+A2)) @ W[K,N] + bias_scale*bias + res_scale*R ; optional relu
// Inner loop uses packed f32x2 FMA: accumulator pairs run along M so the
// 64-bit 'a' operands load directly from shared (no packing); only the TN
// broadcast packs for 'b' are needed.
#define BM 128
#define BN 64
#define BK 16
#define TM 8      // per-thread M (4 f32x2 pairs)
#define TN 4      // per-thread N

__global__ void __launch_bounds__(256)
gemm_kernel(const float* __restrict__ A, const float* __restrict__ A2,
            const float* __restrict__ W, const float* __restrict__ bias,
            float bias_scale,
            const float* __restrict__ R, float res_scale, int relu,
            float* __restrict__ C, int M, int N, int K)
{
    __shared__ float As[BK][BM];   // As[k][m], m contiguous -> 64-bit pair loads
    __shared__ float Bs[BK][BN];
    const int tid = threadIdx.x;
    const int tx = tid & 15;        // 0..15 -> N
    const int ty = tid >> 4;        // 0..15 -> M
    const int m0 = blockIdx.y * BM;
    const int n0 = blockIdx.x * BN;

    u64 acc2[TM/2][TN];            // acc2[i][j] = {C[m0+ty*TM+2i], C[..+2i+1]} col j
    const u64 zz = 0ull;
#pragma unroll
    for (int i = 0; i < TM/2; i++)
#pragma unroll
        for (int j = 0; j < TN; j++) acc2[i][j] = zz;

    const int a_row = tid >> 2;         // 0..63
    const int a_col = (tid & 3) * 4;    // 0,4,8,12
    const int w_row = tid >> 4;         // 0..15
    const int w_col = (tid & 15) * 4;   // 0..60

    for (int k0 = 0; k0 < K; k0 += BK) {
        // load A tile (BM x BK), transpose into As[k][m]
#pragma unroll
        for (int r = 0; r < BM; r += 64) {
            int gm = m0 + a_row + r;
            float4 v = make_float4(0.f, 0.f, 0.f, 0.f);
            if (gm < M) {
                v = *(const float4*)&A[(size_t)gm * K + k0 + a_col];
                if (A2) {
                    float4 v2 = *(const float4*)&A2[(size_t)gm * K + k0 + a_col];
                    v.x += v2.x; v.y += v2.y; v.z += v2.z; v.w += v2.w;
                }
            }
            As[a_col + 0][a_row + r] = v.x;
            As[a_col + 1][a_row + r] = v.y;
            As[a_col + 2][a_row + r] = v.z;
            As[a_col + 3][a_row + r] = v.w;
        }
        // load W tile (BK x BN)
        *(float4*)&Bs[w_row][w_col] =
            *(const float4*)&W[(size_t)(k0 + w_row) * N + n0 + w_col];
        __syncthreads();

#pragma unroll
        for (int k = 0; k < BK; k++) {
            // 4x 64-bit pair loads of A (m-contiguous, 8B-aligned: ty*TM is even)
            const u64* Ap = (const u64*)&As[k][ty * TM];
            u64 ra2[TM/2];
#pragma unroll
            for (int i = 0; i < TM/2; i++) ra2[i] = Ap[i];
            // broadcast-pack the TN b-values
            const float* Bp = &Bs[k][tx * TN];
            u64 rb2[TN];
#pragma unroll
            for (int j = 0; j < TN; j++) rb2[j] = pack2(Bp[j], Bp[j]);
#pragma unroll
            for (int i = 0; i < TM/2; i++)
#pragma unroll
                for (int j = 0; j < TN; j++)
                    fma2(acc2[i][j], ra2[i], rb2[j]);
        }
        __syncthreads();
    }

#pragma unroll
    for (int i = 0; i < TM/2; i++) {
#pragma unroll
        for (int j = 0; j < TN; j++) {
            float clo, chi;
            unpack2(acc2[i][j], clo, chi);
            int gn = n0 + tx * TN + j;
            float bterm = bias_scale * bias[gn];
            int gm_lo = m0 + ty * TM + 2 * i;
            int gm_hi = gm_lo + 1;
            if (gm_lo < M) {
                float c = clo + bterm;
                if (R) c += res_scale * R[(size_t)gm_lo * N + gn];
                if (relu) c = fmaxf(c, 0.f);
                C[(size_t)gm_lo * N + gn] = c;
            }
            if (gm_hi < M) {
                float c = chi + bterm;
                if (R) c += res_scale * R[(size_t)gm_hi * N + gn];
                if (relu) c = fmaxf(c, 0.f);
                C[(size_t)gm_hi * N + gn] = c;
            }
        }
    }
}

// ---------------- reference points: warp-per-query, N=2 --------------------
__global__ void ref_kernel(const float* __restrict__ q,
                           const float* __restrict__ Wr,
                           const float* __restrict__ br,
                           float* __restrict__ ref)
{
    int warp = (blockIdx.x * blockDim.x + threadIdx.x) >> 5;
    int lane = threadIdx.x & 31;
    if (warp >= NQ) return;
    const float* qr = q + (size_t)warp * D;
    float s0 = 0.f, s1 = 0.f;
    for (int j = lane; j < D; j += 32) {
        float qv = qr[j];
        s0 += qv * Wr[j * 2 + 0];
        s1 += qv * Wr[j * 2 + 1];
    }
#pragma unroll
    for (int o = 16; o; o >>= 1) {
        s0 += __shfl_xor_sync(0xffffffffu, s0, o);
        s1 += __shfl_xor_sync(0xffffffffu, s1, o);
    }
    if (lane == 0) {
        s0 += br[0]; s1 += br[1];
        ref[warp * 2 + 0] = 1.f / (1.f + expf(-s0));
        ref[warp * 2 + 1] = 1.f / (1.f + expf(-s1));
    }
}

// ---------------- deformable attention (fused softmax + bilinear gather) ----
// block = one query, warp h handles head h; lane = channel within head (HD=32)
__global__ void __launch_bounds__(256)
deform_kernel(const float* __restrict__ vsum, const float* __restrict__ ref,
              const float* __restrict__ off, const float* __restrict__ attnraw,
              float* __restrict__ out)
{
    const int q = blockIdx.x;
    const int h = threadIdx.x >> 5;
    const int lane = threadIdx.x & 31;

    const float refx = ref[q * 2 + 0];
    const float refy = ref[q * 2 + 1];

    float a = -1e30f, ox = 0.f, oy = 0.f;
    if (lane < NP) {
        a  = attnraw[(size_t)q * (NH*NP) + h * NP + lane];
        ox = off[(size_t)q * (NH*NP*2) + h * (NP*2) + lane * 2 + 0];
        oy = off[(size_t)q * (NH*NP*2) + h * (NP*2) + lane * 2 + 1];
    }
    // softmax over the 8 points (lanes 0..7)
    float m = a;
#pragma unroll
    for (int o = 4; o; o >>= 1) m = fmaxf(m, __shfl_xor_sync(0xffffffffu, m, o));
    float e = expf(a - m);
    float s = e;
#pragma unroll
    for (int o = 4; o; o >>= 1) s += __shfl_xor_sync(0xffffffffu, s, o);
    float w = e / s;

    float locx = refx + ox * (1.f / (float)BEVW);
    float locy = refy + oy * (1.f / (float)BEVH);

    float accv = 0.f;
    const float* vh = vsum + h * HD + lane;
#pragma unroll
    for (int p = 0; p < NP; p++) {
        float x  = __shfl_sync(0xffffffffu, locx, p);
        float y  = __shfl_sync(0xffffffffu, locy, p);
        float wa = __shfl_sync(0xffffffffu, w,    p);
        x = x * (float)BEVW - 0.5f;
        y = y * (float)BEVH - 0.5f;
        float xf = floorf(x), yf = floorf(y);
        float lx = x - xf, ly = y - yf;
        int x0 = (int)xf, y0 = (int)yf;
#pragma unroll
        for (int c = 0; c < 4; c++) {
            int dx = c & 1, dy = c >> 1;
            int ix = x0 + dx, iy = y0 + dy;
            if (ix < 0 || ix >= BEVW || iy < 0 || iy >= BEVH) continue;
            float wc = (dx ? lx : 1.f - lx) * (dy ? ly : 1.f - ly) * wa;
            accv += wc * vh[(size_t)(iy * BEVW + ix) * D];
        }
    }
    out[(size_t)q * D + h * HD + lane] = accv;
}

// ---------------- host launcher --------------------------------------------
extern "C" void kernel_launch(void* const* d_in, const int* in_sizes, int n_in,
                              void* d_out, int out_size)
{
    (void)in_sizes; (void)n_in; (void)out_size;
    const float* B0    = (const float*)d_in[0];
    const float* B1    = (const float*)d_in[1];
    const float* q     = (const float*)d_in[2];
    const float* Wref  = (const float*)d_in[3];
    const float* bref  = (const float*)d_in[4];
    const float* Woff  = (const float*)d_in[5];
    const float* boff  = (const float*)d_in[6];
    const float* Wattn = (const float*)d_in[7];
    const float* battn = (const float*)d_in[8];
    const float* Wval  = (const float*)d_in[9];
    const float* bval  = (const float*)d_in[10];
    const float* Wout  = (const float*)d_in[11];
    const float* bout  = (const float*)d_in[12];
    const float* Wff1  = (const float*)d_in[13];
    const float* bff1  = (const float*)d_in[14];
    const float* Wff2  = (const float*)d_in[15];
    const float* bff2  = (const float*)d_in[16];
    float* out = (float*)d_out;

    float *p_off, *p_attn, *p_ref, *p_vsum, *p_att, *p_ffh;
    cudaGetSymbolAddress((void**)&p_off,  g_off);
    cudaGetSymbolAddress((void**)&p_attn, g_attn);
    cudaGetSymbolAddress((void**)&p_ref,  g_ref);
    cudaGetSymbolAddress((void**)&p_vsum, g_vsum);
    cudaGetSymbolAddress((void**)&p_att,  g_att);
    cudaGetSymbolAddress((void**)&p_ffh,  g_ffh);

    const int MB = (NQ + BM - 1) / BM;  // 313

    // 1) off = q @ W_off + b_off            [40000 x 128]
    gemm_kernel<<<dim3((NH*NP*2)/BN, MB), 256>>>(q, nullptr, Woff, boff, 1.f,
                                                 nullptr, 0.f, 0, p_off, NQ, NH*NP*2, D);
    // 2) attnraw = q @ W_attn + b_attn      [40000 x 64]
    gemm_kernel<<<dim3((NH*NP)/BN, MB), 256>>>(q, nullptr, Wattn, battn, 1.f,
                                               nullptr, 0.f, 0, p_attn, NQ, NH*NP, D);
    // 3) ref = sigmoid(q @ W_ref + b_ref)   [40000 x 2]
    ref_kernel<<<(NQ * 32 + 255) / 256, 256>>>(q, Wref, bref, p_ref);

    // 4) vsum = (B0 + B1) @ W_val + 2*b_val [40000 x 256]
    //    (linear => deform(val0)+deform(val1) == deform(vsum))
    gemm_kernel<<<dim3(D/BN, MB), 256>>>(B0, B1, Wval, bval, 2.f,
                                         nullptr, 0.f, 0, p_vsum, NQ, D, D);
    // 5) attended-sum via fused softmax + bilinear gather
    deform_kernel<<<NQ, 256>>>(p_vsum, p_ref, p_off, p_attn, p_att);

    // 6) B_short = att @ W_out + 2*b_out + 2*q   -> d_out
    gemm_kernel<<<dim3(D/BN, MB), 256>>>(p_att, nullptr, Wout, bout, 2.f,
                                         q, 2.f, 0, out, NQ, D, D);
    // 7) h = relu(B_short @ W_ffn1 + b_ffn1)     [40000 x 1024]
    gemm_kernel<<<dim3(DFF/BN, MB), 256>>>(out, nullptr, Wff1, bff1, 1.f,
                                           nullptr, 0.f, 1, p_ffh, NQ, DFF, D);
    // 8) out = h @ W_ffn2 + b_ffn2 + B_short     -> d_out (in-place residual)
    gemm_kernel<<<dim3(D/BN, MB), 256>>>(p_ffh, nullptr, Wff2, bff2, 1.f,
                                         out, 1.f, 0, out, NQ, D, DFF);
}